// round 4
// baseline (speedup 1.0000x reference)
#include <cuda_runtime.h>
#include <cstdint>

// EdgewiseReduce: out[dst[e], :] += 0.5 * edge_data[e, :], D=32, E=1.6M, N=100K.
// Round-4 strategy: replace per-lane red.global.add.v4 (12.8M l1tex lane-wavefronts,
// the measured binder) with TMA bulk reductions: one 128B
// cp.reduce.async.bulk.add.f32 per EDGE (1.6M async ops), staged through SMEM.

#define FACTOR 0.5f
#define D 32

__device__ __forceinline__ uint32_t smem_u32(const void* p) {
    uint32_t a;
    asm("{ .reg .u64 t; cvta.to.shared.u64 t, %1; cvt.u32.u64 %0, t; }"
        : "=r"(a) : "l"(p));
    return a;
}

__global__ void __launch_bounds__(256, 4) scatter_tma_kernel(
    const float4* __restrict__ edge_data,
    const int* __restrict__ edge_dst,
    float* __restrict__ out,
    int num_edges)
{
    // Per-warp double-buffered staging: 8 edges x 128B per buffer.
    __shared__ __align__(1024) float4 stage[8][2][64];  // [warp][buf][chunk] = 16KB

    const int warp = threadIdx.x >> 5;
    const int lane = threadIdx.x & 31;
    const int gwarp = blockIdx.x * 8 + warp;
    const int nwarps = gridDim.x * 8;

    const int ngroups = num_edges >> 3;   // groups of 8 edges
    int issued = 0;
    int buf = 0;

    for (int g = gwarp; g < ngroups; g += nwarps) {
        const int eg = g << 3;            // first edge of group
        const int cbase = eg << 3;        // first float4 chunk (fits int32: <=12.8M)

        // Flow control: buffer `buf` was used by the group issued 2 iters ago.
        // Each issuing lane commits 1 group/iter; wait until <=1 of mine remain.
        if (issued >= 2 && lane < 8)
            asm volatile("cp.async.bulk.wait_group 1;" ::: "memory");
        __syncwarp();

        // Coalesced load of 8 edges (64 float4 chunks), premultiply, stage.
        float4 v0 = edge_data[cbase + lane];
        float4 v1 = edge_data[cbase + 32 + lane];
        v0.x *= FACTOR; v0.y *= FACTOR; v0.z *= FACTOR; v0.w *= FACTOR;
        v1.x *= FACTOR; v1.y *= FACTOR; v1.z *= FACTOR; v1.w *= FACTOR;
        stage[warp][buf][lane]      = v0;
        stage[warp][buf][32 + lane] = v1;

        int dst = 0;
        if (lane < 8) dst = edge_dst[eg + lane];
        __syncwarp();

        // Lanes 0-7: one 128B bulk-reduce (add.f32) per edge row.
        if (lane < 8) {
            asm volatile("fence.proxy.async.shared::cta;" ::: "memory");
            uint32_t sptr = smem_u32(&stage[warp][buf][lane << 3]);
            float* gptr = out + (size_t)dst * D;
            asm volatile(
                "cp.reduce.async.bulk.global.shared::cta.bulk_group.add.f32 "
                "[%0], [%1], %2;"
                :: "l"(gptr), "r"(sptr), "n"(D * 4) : "memory");
            asm volatile("cp.async.bulk.commit_group;" ::: "memory");
        }
        buf ^= 1;
        issued++;
    }
    if (issued > 0 && lane < 8)
        asm volatile("cp.async.bulk.wait_group 0;" ::: "memory");

    // Tail edges (num_edges % 8): plain per-chunk RED (empty for E=1.6M).
    const int tail_chunk0 = ngroups << 6;       // ngroups*8 edges * 8 chunks
    const int total_chunks = num_edges << 3;
    for (int i = tail_chunk0 + blockIdx.x * blockDim.x + threadIdx.x;
         i < total_chunks; i += gridDim.x * blockDim.x) {
        int e = i >> 3, c = i & 7;
        int dst = edge_dst[e];
        float4 v = edge_data[i];
        float* p = out + (size_t)dst * D + c * 4;
        asm volatile("red.global.add.v4.f32 [%0], {%1, %2, %3, %4};"
                     :: "l"(p), "f"(v.x * FACTOR), "f"(v.y * FACTOR),
                        "f"(v.z * FACTOR), "f"(v.w * FACTOR) : "memory");
    }
}

extern "C" void kernel_launch(void* const* d_in, const int* in_sizes, int n_in,
                              void* d_out, int out_size) {
    const float4* edge_data = (const float4*)d_in[0];
    const int*    edge_dst  = (const int*)d_in[1];
    float* out = (float*)d_out;

    int num_edges = in_sizes[1];   // E

    // 1) Zero output via graph-capturable memset node (harness poisons with 0xAA).
    cudaMemsetAsync(d_out, 0, (size_t)out_size * sizeof(float), 0);

    // 2) TMA bulk-reduce scatter: 8 edges per warp-iteration, grid-stride.
    int blocks = 2048;
    int ngroups = num_edges >> 3;
    int want = (ngroups + 7) / 8;            // one iteration per warp minimum
    if (blocks > want) blocks = want < 1 ? 1 : want;
    scatter_tma_kernel<<<blocks, 256>>>(edge_data, edge_dst, out, num_edges);
}